// round 12
// baseline (speedup 1.0000x reference)
#include <cuda_runtime.h>
#include <cuda_bf16.h>
#include <cstdint>

// Problem constants (fixed by setup_inputs)
#define B_   16
#define G_   20000
#define D_   256
#define K_   2048
#define NTOK (K_ + 1)

// GEMM tiling (R9 memory structure)
#define MT   128   // block tile M (genes)
#define NT   256   // block tile N (full output dim)
#define KC   32    // K chunk
#define ST   4     // cp.async stages
#define WS_STRIDE 36                 // ws [n][k] row stride (floats)
#define WS_BUF (NT * WS_STRIDE)      // 9216 floats per stage (36 KB)
#define HS_STRIDE 36                 // hs [m][k] row stride (floats)
#define HS_BUF (MT * HS_STRIDE)      // 4608 floats per buffer (18 KB)

// Select kernel
#define SEL_T 1024
#define CH    20     // floats per thread; 1000 threads cover G exactly
#define SEL_ACT 1000 // active loader threads

// Device scratch
__device__ int g_sel_idx[B_ * K_];
__device__ int g_nsel[B_];

__device__ __forceinline__ uint32_t f2tf32(float x) {
    uint32_t r;
    asm("cvt.rna.tf32.f32 %0, %1;" : "=r"(r) : "f"(x));
    return r;
}

__device__ __forceinline__ uint32_t smem_u32(const void* p) {
    uint32_t a;
    asm("{ .reg .u64 t; cvta.to.shared.u64 t, %1; cvt.u32.u64 %0, t; }"
        : "=r"(a) : "l"(p));
    return a;
}

#define CP_ASYNC16(dst_u32, src_ptr) \
    asm volatile("cp.async.cg.shared.global [%0], [%1], 16;" \
                 :: "r"(dst_u32), "l"(src_ptr) : "memory")
#define CP_COMMIT() asm volatile("cp.async.commit_group;" ::: "memory")
#define CP_WAIT(n)  asm volatile("cp.async.wait_group %0;" :: "n"(n) : "memory")

__device__ __forceinline__ void mma_tf32(float& c0, float& c1, float& c2, float& c3,
                                         uint32_t a0, uint32_t a1, uint32_t a2, uint32_t a3,
                                         uint32_t b0, uint32_t b1) {
    asm volatile(
        "mma.sync.aligned.m16n8k8.row.col.f32.tf32.tf32.f32 "
        "{%0,%1,%2,%3}, {%4,%5,%6,%7}, {%8,%9}, {%0,%1,%2,%3};"
        : "+f"(c0), "+f"(c1), "+f"(c2), "+f"(c3)
        : "r"(a0), "r"(a1), "r"(a2), "r"(a3), "r"(b0), "r"(b1));
}

// Fast exact-erf GELU: A&S 7.1.26 rational approx, abs err ~1e-6 (negligible
// vs tf32 rounding). ~12 instr vs erff's ~20+.
__device__ __forceinline__ float gelu_fast(float x) {
    const float u = x * 0.70710678118654752f;
    const float au = fabsf(u);
    const float t = __frcp_rn(fmaf(0.3275911f, au, 1.0f));
    float p = fmaf(t, 1.061405429f, -1.453152027f);
    p = fmaf(t, p, 1.421413741f);
    p = fmaf(t, p, -0.284496736f);
    p = fmaf(t, p, 0.254829592f);
    const float e = __expf(-au * au);
    float erf_au = fmaf(-t * p, e, 1.0f);     // erf(|u|)
    const float erf_u = copysignf(erf_au, u);
    return 0.5f * x * (1.0f + erf_u);
}

// ---------------------------------------------------------------------------
// Kernel A: per-batch exact top-K selection + compaction + CLS row + mask.
// (R11 verbatim) 32-bit key = ~bits(expr); ties via explicit tie-rank.
// Per-warp private histograms; aligned float4 register loads; shfl scans.
// ---------------------------------------------------------------------------
__global__ __launch_bounds__(SEL_T) void select_kernel(const float* __restrict__ expr,
                                                       const float* __restrict__ cls,
                                                       float* __restrict__ out,
                                                       long long out_size) {
    const int b = blockIdx.x;
    const float* ex = expr + (size_t)b * G_;
    const int t = threadIdx.x;
    const int lane = t & 31;
    const int wrp = t >> 5;
    const int start = t * CH;
    const bool active = (t < SEL_ACT);

    float v[CH];
    if (active) {
        const float4* p = (const float4*)(ex + start);
#pragma unroll
        for (int q = 0; q < 5; ++q) {
            const float4 f = __ldg(p + q);
            v[4 * q + 0] = f.x; v[4 * q + 1] = f.y;
            v[4 * q + 2] = f.z; v[4 * q + 3] = f.w;
        }
    } else {
#pragma unroll
        for (int i = 0; i < CH; ++i) v[i] = 0.0f;
    }

    __shared__ uint32_t ph[32 * 256];   // per-warp private histograms (32 KB)
    __shared__ int warp_sums[32];
    __shared__ unsigned int s_pref;
    __shared__ int s_rem;
    __shared__ int s_total;

    if (t == 0) { s_pref = 0u; s_rem = K_; }
    __syncthreads();

    uint32_t* myh = ph + wrp * 256;

    for (int round = 0; round < 4; ++round) {
        const int shift = 24 - 8 * round;
#pragma unroll
        for (int i = t; i < 32 * 256; i += SEL_T) ph[i] = 0;
        __syncthreads();
        const unsigned int pref = s_pref;
        const int rem = s_rem;
#pragma unroll
        for (int i = 0; i < CH; ++i) {
            const unsigned int key = ~__float_as_uint(v[i]);
            bool valid = active;
            if (round > 0) valid = valid && (((key ^ pref) >> (shift + 8)) == 0);
            const unsigned int bucket = valid ? ((key >> shift) & 255u) : 0x10000u;
            const unsigned int mask = __match_any_sync(0xFFFFFFFFu, bucket);
            const int leader = __ffs(mask) - 1;
            if (valid && lane == leader) myh[bucket] += __popc(mask);
        }
        __syncthreads();
        if (t < 256) {
            uint32_t mine = 0;
#pragma unroll
            for (int w = 0; w < 32; ++w) mine += ph[w * 256 + t];
            unsigned int incl = mine;
#pragma unroll
            for (int o = 1; o < 32; o <<= 1) {
                unsigned int n = __shfl_up_sync(0xFFFFFFFFu, incl, o);
                if (lane >= o) incl += n;
            }
            if (lane == 31) warp_sums[wrp] = (int)incl;
            __syncthreads();
            unsigned int add = 0;
            for (int i = 0; i < wrp; ++i) add += (unsigned int)warp_sums[i];
            incl += add;
            const unsigned int excl = incl - mine;
            if ((int)excl < rem && rem <= (int)incl) {
                s_pref = pref | ((unsigned int)t << shift);
                s_rem = rem - (int)excl;
            }
        } else {
            __syncthreads();
        }
        __syncthreads();
    }
    const unsigned int T = s_pref;
    const int r = s_rem;
    const float tval = __uint_as_float(~T);
    const bool tie_pos = (tval > 0.0f);

    int cnt_less = 0, cnt_tie = 0;
    if (active) {
#pragma unroll
        for (int i = 0; i < CH; ++i) {
            const unsigned int key = ~__float_as_uint(v[i]);
            if (key < T) { if (v[i] > 0.0f) cnt_less++; }
            else if (key == T) cnt_tie++;
        }
    }

    int tie_excl;
    {
        int incl = cnt_tie;
#pragma unroll
        for (int o = 1; o < 32; o <<= 1) {
            int n = __shfl_up_sync(0xFFFFFFFFu, incl, o);
            if (lane >= o) incl += n;
        }
        if (lane == 31) warp_sums[wrp] = incl;
        __syncthreads();
        if (wrp == 0) {
            int s = warp_sums[lane];
#pragma unroll
            for (int o = 1; o < 32; o <<= 1) {
                int n = __shfl_up_sync(0xFFFFFFFFu, s, o);
                if (lane >= o) s += n;
            }
            warp_sums[lane] = s;
        }
        __syncthreads();
        const int add = (wrp > 0) ? warp_sums[wrp - 1] : 0;
        tie_excl = incl + add - cnt_tie;
    }

    int kept_ties = r - tie_excl;
    if (kept_ties < 0) kept_ties = 0;
    if (kept_ties > cnt_tie) kept_ties = cnt_tie;
    if (!tie_pos) kept_ties = 0;
    const int cnt_keep = cnt_less + kept_ties;

    __syncthreads();
    int pos, ns;
    {
        int incl = cnt_keep;
#pragma unroll
        for (int o = 1; o < 32; o <<= 1) {
            int n = __shfl_up_sync(0xFFFFFFFFu, incl, o);
            if (lane >= o) incl += n;
        }
        if (lane == 31) warp_sums[wrp] = incl;
        __syncthreads();
        if (wrp == 0) {
            int s = warp_sums[lane];
#pragma unroll
            for (int o = 1; o < 32; o <<= 1) {
                int n = __shfl_up_sync(0xFFFFFFFFu, s, o);
                if (lane >= o) s += n;
            }
            warp_sums[lane] = s;
            if (lane == 31) s_total = s;
        }
        __syncthreads();
        const int add = (wrp > 0) ? warp_sums[wrp - 1] : 0;
        pos = incl + add - cnt_keep;
        ns = s_total;
    }

    if (active) {
        int tie_seen = tie_excl;
#pragma unroll
        for (int i = 0; i < CH; ++i) {
            const int g = start + i;
            const unsigned int key = ~__float_as_uint(v[i]);
            if (key < T) {
                if (v[i] > 0.0f) g_sel_idx[b * K_ + (pos++)] = g;
            } else if (key == T) {
                if (tie_seen < r && tie_pos) g_sel_idx[b * K_ + (pos++)] = g;
                tie_seen++;
            }
        }
    }
    if (t == 0) g_nsel[b] = ns;

    if (t < D_) out[(size_t)b * NTOK * D_ + t] = cls[t];
    const long long TOK = (long long)B_ * NTOK * D_;
    if (out_size >= TOK + (long long)B_ * NTOK) {
        for (int s = t; s < NTOK; s += SEL_T) {
            float m = (s == 0) ? 1.0f : (((s - 1) < ns) ? 1.0f : 0.0f);
            out[TOK + (long long)b * NTOK + s] = m;
        }
    }
}

// ---------------------------------------------------------------------------
// Kernel B: fused gelu + tf32 mma.sync GEMM + epilogue.
// R9 memory structure; per-chunk order now: cp-issue -> MMA(c) -> gelu(c+1),
// so tensor work leads the chunk and gelu's latency drains into the barrier.
// gelu uses the fast exact-erf approximation.
// ---------------------------------------------------------------------------
__global__ __launch_bounds__(512, 1) void tok_mma_kernel(
    const float* __restrict__ expr, const float* __restrict__ gene_emb,
    const float* __restrict__ w1, const float* __restrict__ b1,
    const float* __restrict__ w2, const float* __restrict__ b2,
    float* __restrict__ out) {
    extern __shared__ uint32_t dynsm[];
    uint32_t* hs = dynsm;                    // 2 x [MT][HS_STRIDE]
    uint32_t* ws = dynsm + 2 * HS_BUF;       // ST x [NT][WS_STRIDE]
    __shared__ float se[MT];
    __shared__ int   sg[MT];

    const int tid  = threadIdx.x;
    const int lane = tid & 31;
    const int warp = tid >> 5;
    const int gq   = lane >> 2;   // 0..7
    const int tq   = lane & 3;    // 0..3
    const int wm   = warp & 3;    // m warp group
    const int wn   = warp >> 2;   // n warp group

    const int b  = blockIdx.y;
    const int j0 = blockIdx.x * MT;

    // Prologue: gather selected genes
    if (tid < MT) {
        const int ns = g_nsel[b];
        const int j = j0 + tid;
        if (j < ns) {
            int g = g_sel_idx[b * K_ + j];
            sg[tid] = g;
            se[tid] = expr[(size_t)b * G_ + g];
        } else {
            sg[tid] = -1;
            se[tid] = 0.0f;
        }
    }

    // cp.async thread map: 4 x 16B per thread per chunk
    uint32_t cp_dst[4];
    const float* cp_src[4];
#pragma unroll
    for (int it = 0; it < 4; ++it) {
        const int idx = tid + it * 512;
        const int n = idx >> 3;
        const int seg = idx & 7;
        cp_dst[it] = smem_u32(ws + n * WS_STRIDE + seg * 4);
        cp_src[it] = w2 + (size_t)n * D_ + seg * 4;
    }

    // issue w2 chunks 0..ST-2
#pragma unroll
    for (int c = 0; c < ST - 1; ++c) {
#pragma unroll
        for (int it = 0; it < 4; ++it)
            CP_ASYNC16(cp_dst[it] + (c % ST) * WS_BUF * 4, cp_src[it] + c * KC);
        CP_COMMIT();
    }
    __syncthreads();   // se/sg visible

    // stage h chunk 0 into hs buffer 0
    const int hm = tid >> 2;            // gene row
    const int hk = (tid & 3) * 8;       // k offset within chunk
    const float e_m = se[hm];
    {
        uint32_t* hrow = hs + hm * HS_STRIDE + hk;
#pragma unroll
        for (int j = 0; j < 8; ++j) {
            const float x = fmaf(e_m, __ldg(&w1[hk + j]), __ldg(&b1[hk + j]));
            hrow[j] = f2tf32(gelu_fast(x));
        }
    }

    float acc[2][8][4];
#pragma unroll
    for (int mi = 0; mi < 2; ++mi)
#pragma unroll
        for (int ni = 0; ni < 8; ++ni)
#pragma unroll
            for (int q = 0; q < 4; ++q) acc[mi][ni][q] = 0.0f;

    __syncthreads();   // h(0) visible

#pragma unroll
    for (int c = 0; c < 8; ++c) {
        // ensure w2 chunk c landed
        if (c <= 5) CP_WAIT(2);
        else if (c == 6) CP_WAIT(1);
        else CP_WAIT(0);
        __syncthreads();   // visibility + closes prior chunk's smem reads

        // issue w2 chunk c+ST-1 (buffer consumed in iter c-1; safe after barrier)
        if (c + ST - 1 < 8) {
#pragma unroll
            for (int it = 0; it < 4; ++it)
                CP_ASYNC16(cp_dst[it] + ((c + ST - 1) % ST) * WS_BUF * 4,
                           cp_src[it] + (c + ST - 1) * KC);
            CP_COMMIT();
        }

        // MMAs on chunk c FIRST (tensor pipe leads the chunk)
        {
            const uint32_t* hbuf = hs + (c & 1) * HS_BUF;
            const uint32_t* wbuf = ws + (c % ST) * WS_BUF;
#pragma unroll
            for (int ks = 0; ks < 4; ++ks) {
                const int k8 = ks * 8;
                uint32_t a[2][4];
#pragma unroll
                for (int mi = 0; mi < 2; ++mi) {
                    const int rm = wm * 32 + mi * 16;
                    a[mi][0] = hbuf[(rm + gq) * HS_STRIDE + k8 + tq];
                    a[mi][1] = hbuf[(rm + 8 + gq) * HS_STRIDE + k8 + tq];
                    a[mi][2] = hbuf[(rm + gq) * HS_STRIDE + k8 + tq + 4];
                    a[mi][3] = hbuf[(rm + 8 + gq) * HS_STRIDE + k8 + tq + 4];
                }
#pragma unroll
                for (int ni = 0; ni < 8; ++ni) {
                    const int nc = wn * 64 + ni * 8 + gq;
                    const uint32_t b0 = wbuf[nc * WS_STRIDE + k8 + tq];
                    const uint32_t b1r = wbuf[nc * WS_STRIDE + k8 + tq + 4];
#pragma unroll
                    for (int mi = 0; mi < 2; ++mi)
                        mma_tf32(acc[mi][ni][0], acc[mi][ni][1], acc[mi][ni][2], acc[mi][ni][3],
                                 a[mi][0], a[mi][1], a[mi][2], a[mi][3], b0, b1r);
                }
            }
        }

        // stage h chunk c+1 into the other hs buffer (drains into the barrier)
        if (c + 1 < 8) {
            const int k0 = (c + 1) * KC + hk;
            uint32_t* hrow = hs + ((c + 1) & 1) * HS_BUF + hm * HS_STRIDE + hk;
#pragma unroll
            for (int j = 0; j < 8; ++j) {
                const float x = fmaf(e_m, __ldg(&w1[k0 + j]), __ldg(&b1[k0 + j]));
                hrow[j] = f2tf32(gelu_fast(x));
            }
        }
    }

    // Epilogue: + b2 + gene_emb, zero invalid rows.
    float2 bb[8];
#pragma unroll
    for (int ni = 0; ni < 8; ++ni)
        bb[ni] = __ldg((const float2*)(b2 + wn * 64 + ni * 8 + 2 * tq));

#pragma unroll
    for (int mi = 0; mi < 2; ++mi) {
#pragma unroll
        for (int rr = 0; rr < 2; ++rr) {
            const int rrow = wm * 32 + mi * 16 + rr * 8 + gq;
            const int g = sg[rrow];
            float* orow = out + ((size_t)b * NTOK + 1 + j0 + rrow) * D_;
            if (g >= 0) {
                const float* gerow = gene_emb + (size_t)g * D_;
#pragma unroll
                for (int ni = 0; ni < 8; ++ni) {
                    const int col = wn * 64 + ni * 8 + 2 * tq;
                    const float2 ge = __ldg((const float2*)(gerow + col));
                    float2 rv;
                    rv.x = acc[mi][ni][2 * rr + 0] + bb[ni].x + ge.x;
                    rv.y = acc[mi][ni][2 * rr + 1] + bb[ni].y + ge.y;
                    *(float2*)(orow + col) = rv;
                }
            } else {
                const float2 z = make_float2(0.f, 0.f);
#pragma unroll
                for (int ni = 0; ni < 8; ++ni) {
                    const int col = wn * 64 + ni * 8 + 2 * tq;
                    *(float2*)(orow + col) = z;
                }
            }
        }
    }
}

// ---------------------------------------------------------------------------
extern "C" void kernel_launch(void* const* d_in, const int* in_sizes, int n_in,
                              void* d_out, int out_size) {
    const float* expr     = (const float*)d_in[0];
    const float* gene_emb = (const float*)d_in[1];
    const float* w1       = (const float*)d_in[2];
    const float* b1       = (const float*)d_in[3];
    const float* w2       = (const float*)d_in[4];
    const float* b2       = (const float*)d_in[5];
    const float* cls      = (const float*)d_in[6];
    float* out = (float*)d_out;

    const int tok_smem = (2 * HS_BUF + ST * WS_BUF) * (int)sizeof(uint32_t);  // 180 KB
    cudaFuncSetAttribute(tok_mma_kernel, cudaFuncAttributeMaxDynamicSharedMemorySize,
                         tok_smem);

    select_kernel<<<B_, SEL_T>>>(expr, cls, out, (long long)out_size);
    tok_mma_kernel<<<dim3(K_ / MT, B_), 512, tok_smem>>>(expr, gene_emb, w1, b1,
                                                         w2, b2, out);
}

// round 15
// speedup vs baseline: 1.0653x; 1.0653x over previous
#include <cuda_runtime.h>
#include <cuda_bf16.h>
#include <cstdint>

// Problem constants (fixed by setup_inputs)
#define B_   16
#define G_   20000
#define D_   256
#define K_   2048
#define NTOK (K_ + 1)

// GEMM tiling: MT=64 x NT=256, 256 threads, 2 CTAs/SM
#define MT   64    // block tile M (genes)
#define NT   256   // block tile N (full output dim)
#define KC   32    // K chunk
#define ST   2     // cp.async stages (smem-limited at 2 CTAs/SM)
#define WS_STRIDE 36                 // ws [n][k] row stride (floats)
#define WS_BUF (NT * WS_STRIDE)      // 9216 floats per stage (36 KB)
#define HS_STRIDE 36                 // hs [m][k] row stride (floats)
#define HS_BUF (MT * HS_STRIDE)      // 2304 floats per buffer (9 KB)

// Select kernel
#define SEL_T 1024
#define CH    20     // floats per thread; 1000 threads cover G exactly
#define SEL_ACT 1000 // active loader threads

// Device scratch
__device__ int g_sel_idx[B_ * K_];
__device__ int g_nsel[B_];

__device__ __forceinline__ uint32_t f2tf32(float x) {
    uint32_t r;
    asm("cvt.rna.tf32.f32 %0, %1;" : "=r"(r) : "f"(x));
    return r;
}

__device__ __forceinline__ uint32_t smem_u32(const void* p) {
    uint32_t a;
    asm("{ .reg .u64 t; cvta.to.shared.u64 t, %1; cvt.u32.u64 %0, t; }"
        : "=r"(a) : "l"(p));
    return a;
}

#define CP_ASYNC16(dst_u32, src_ptr) \
    asm volatile("cp.async.cg.shared.global [%0], [%1], 16;" \
                 :: "r"(dst_u32), "l"(src_ptr) : "memory")
#define CP_COMMIT() asm volatile("cp.async.commit_group;" ::: "memory")
#define CP_WAIT(n)  asm volatile("cp.async.wait_group %0;" :: "n"(n) : "memory")

__device__ __forceinline__ void mma_tf32(float& c0, float& c1, float& c2, float& c3,
                                         uint32_t a0, uint32_t a1, uint32_t a2, uint32_t a3,
                                         uint32_t b0, uint32_t b1) {
    asm volatile(
        "mma.sync.aligned.m16n8k8.row.col.f32.tf32.tf32.f32 "
        "{%0,%1,%2,%3}, {%4,%5,%6,%7}, {%8,%9}, {%0,%1,%2,%3};"
        : "+f"(c0), "+f"(c1), "+f"(c2), "+f"(c3)
        : "r"(a0), "r"(a1), "r"(a2), "r"(a3), "r"(b0), "r"(b1));
}

__device__ __forceinline__ float gelu_exact(float x) {
    return 0.5f * x * (1.0f + erff(x * 0.70710678118654752f));
}

// ---------------------------------------------------------------------------
// Kernel A: per-batch exact top-K selection + compaction + CLS row + mask.
// (R11 verbatim) 32-bit key = ~bits(expr); ties via explicit tie-rank.
// Per-warp private histograms; aligned float4 register loads; shfl scans.
// ---------------------------------------------------------------------------
__global__ __launch_bounds__(SEL_T) void select_kernel(const float* __restrict__ expr,
                                                       const float* __restrict__ cls,
                                                       float* __restrict__ out,
                                                       long long out_size) {
    const int b = blockIdx.x;
    const float* ex = expr + (size_t)b * G_;
    const int t = threadIdx.x;
    const int lane = t & 31;
    const int wrp = t >> 5;
    const int start = t * CH;
    const bool active = (t < SEL_ACT);

    float v[CH];
    if (active) {
        const float4* p = (const float4*)(ex + start);
#pragma unroll
        for (int q = 0; q < 5; ++q) {
            const float4 f = __ldg(p + q);
            v[4 * q + 0] = f.x; v[4 * q + 1] = f.y;
            v[4 * q + 2] = f.z; v[4 * q + 3] = f.w;
        }
    } else {
#pragma unroll
        for (int i = 0; i < CH; ++i) v[i] = 0.0f;
    }

    __shared__ uint32_t ph[32 * 256];   // per-warp private histograms (32 KB)
    __shared__ int warp_sums[32];
    __shared__ unsigned int s_pref;
    __shared__ int s_rem;
    __shared__ int s_total;

    if (t == 0) { s_pref = 0u; s_rem = K_; }
    __syncthreads();

    uint32_t* myh = ph + wrp * 256;

    for (int round = 0; round < 4; ++round) {
        const int shift = 24 - 8 * round;
#pragma unroll
        for (int i = t; i < 32 * 256; i += SEL_T) ph[i] = 0;
        __syncthreads();
        const unsigned int pref = s_pref;
        const int rem = s_rem;
#pragma unroll
        for (int i = 0; i < CH; ++i) {
            const unsigned int key = ~__float_as_uint(v[i]);
            bool valid = active;
            if (round > 0) valid = valid && (((key ^ pref) >> (shift + 8)) == 0);
            const unsigned int bucket = valid ? ((key >> shift) & 255u) : 0x10000u;
            const unsigned int mask = __match_any_sync(0xFFFFFFFFu, bucket);
            const int leader = __ffs(mask) - 1;
            if (valid && lane == leader) myh[bucket] += __popc(mask);
        }
        __syncthreads();
        if (t < 256) {
            uint32_t mine = 0;
#pragma unroll
            for (int w = 0; w < 32; ++w) mine += ph[w * 256 + t];
            unsigned int incl = mine;
#pragma unroll
            for (int o = 1; o < 32; o <<= 1) {
                unsigned int n = __shfl_up_sync(0xFFFFFFFFu, incl, o);
                if (lane >= o) incl += n;
            }
            if (lane == 31) warp_sums[wrp] = (int)incl;
            __syncthreads();
            unsigned int add = 0;
            for (int i = 0; i < wrp; ++i) add += (unsigned int)warp_sums[i];
            incl += add;
            const unsigned int excl = incl - mine;
            if ((int)excl < rem && rem <= (int)incl) {
                s_pref = pref | ((unsigned int)t << shift);
                s_rem = rem - (int)excl;
            }
        } else {
            __syncthreads();
        }
        __syncthreads();
    }
    const unsigned int T = s_pref;
    const int r = s_rem;
    const float tval = __uint_as_float(~T);
    const bool tie_pos = (tval > 0.0f);

    int cnt_less = 0, cnt_tie = 0;
    if (active) {
#pragma unroll
        for (int i = 0; i < CH; ++i) {
            const unsigned int key = ~__float_as_uint(v[i]);
            if (key < T) { if (v[i] > 0.0f) cnt_less++; }
            else if (key == T) cnt_tie++;
        }
    }

    int tie_excl;
    {
        int incl = cnt_tie;
#pragma unroll
        for (int o = 1; o < 32; o <<= 1) {
            int n = __shfl_up_sync(0xFFFFFFFFu, incl, o);
            if (lane >= o) incl += n;
        }
        if (lane == 31) warp_sums[wrp] = incl;
        __syncthreads();
        if (wrp == 0) {
            int s = warp_sums[lane];
#pragma unroll
            for (int o = 1; o < 32; o <<= 1) {
                int n = __shfl_up_sync(0xFFFFFFFFu, s, o);
                if (lane >= o) s += n;
            }
            warp_sums[lane] = s;
        }
        __syncthreads();
        const int add = (wrp > 0) ? warp_sums[wrp - 1] : 0;
        tie_excl = incl + add - cnt_tie;
    }

    int kept_ties = r - tie_excl;
    if (kept_ties < 0) kept_ties = 0;
    if (kept_ties > cnt_tie) kept_ties = cnt_tie;
    if (!tie_pos) kept_ties = 0;
    const int cnt_keep = cnt_less + kept_ties;

    __syncthreads();
    int pos, ns;
    {
        int incl = cnt_keep;
#pragma unroll
        for (int o = 1; o < 32; o <<= 1) {
            int n = __shfl_up_sync(0xFFFFFFFFu, incl, o);
            if (lane >= o) incl += n;
        }
        if (lane == 31) warp_sums[wrp] = incl;
        __syncthreads();
        if (wrp == 0) {
            int s = warp_sums[lane];
#pragma unroll
            for (int o = 1; o < 32; o <<= 1) {
                int n = __shfl_up_sync(0xFFFFFFFFu, s, o);
                if (lane >= o) s += n;
            }
            warp_sums[lane] = s;
            if (lane == 31) s_total = s;
        }
        __syncthreads();
        const int add = (wrp > 0) ? warp_sums[wrp - 1] : 0;
        pos = incl + add - cnt_keep;
        ns = s_total;
    }

    if (active) {
        int tie_seen = tie_excl;
#pragma unroll
        for (int i = 0; i < CH; ++i) {
            const int g = start + i;
            const unsigned int key = ~__float_as_uint(v[i]);
            if (key < T) {
                if (v[i] > 0.0f) g_sel_idx[b * K_ + (pos++)] = g;
            } else if (key == T) {
                if (tie_seen < r && tie_pos) g_sel_idx[b * K_ + (pos++)] = g;
                tie_seen++;
            }
        }
    }
    if (t == 0) g_nsel[b] = ns;

    if (t < D_) out[(size_t)b * NTOK * D_ + t] = cls[t];
    const long long TOK = (long long)B_ * NTOK * D_;
    if (out_size >= TOK + (long long)B_ * NTOK) {
        for (int s = t; s < NTOK; s += SEL_T) {
            float m = (s == 0) ? 1.0f : (((s - 1) < ns) ? 1.0f : 0.0f);
            out[TOK + (long long)b * NTOK + s] = m;
        }
    }
}

// ---------------------------------------------------------------------------
// Kernel B: fused gelu + tf32 mma.sync GEMM + epilogue.
// MT=64 x NT=256, 256 threads, 2 CTAs/SM (cross-CTA stall overlap, no gelu
// duplication). w2 via 2-stage cp.async; h double-buffered, gelu interleaved
// (R11 per-chunk order: cp-issue -> gelu(c+1) -> MMA(c)).
// 8 warps = 2m x 4n, warp tile 32x64. A RNA-tf32, B HW-truncated tf32.
// ---------------------------------------------------------------------------
__global__ __launch_bounds__(256, 2) void tok_mma_kernel(
    const float* __restrict__ expr, const float* __restrict__ gene_emb,
    const float* __restrict__ w1, const float* __restrict__ b1,
    const float* __restrict__ w2, const float* __restrict__ b2,
    float* __restrict__ out) {
    extern __shared__ uint32_t dynsm[];
    uint32_t* hs = dynsm;                    // 2 x [MT][HS_STRIDE]
    uint32_t* ws = dynsm + 2 * HS_BUF;       // ST x [NT][WS_STRIDE]
    __shared__ float se[MT];
    __shared__ int   sg[MT];

    const int tid  = threadIdx.x;
    const int lane = tid & 31;
    const int warp = tid >> 5;
    const int gq   = lane >> 2;   // 0..7
    const int tq   = lane & 3;    // 0..3
    const int wm   = warp & 1;    // m warp group (0..1)
    const int wn   = warp >> 1;   // n warp group (0..3)

    const int b  = blockIdx.y;
    const int j0 = blockIdx.x * MT;

    // Prologue: gather selected genes
    if (tid < MT) {
        const int ns = g_nsel[b];
        const int j = j0 + tid;
        if (j < ns) {
            int g = g_sel_idx[b * K_ + j];
            sg[tid] = g;
            se[tid] = expr[(size_t)b * G_ + g];
        } else {
            sg[tid] = -1;
            se[tid] = 0.0f;
        }
    }

    // cp.async map: 8 x 16B per thread per chunk, register-lean strided form.
    // segment idx = tid + it*256; n = idx>>3 = (tid>>3) + 32*it; seg = tid&7.
    const int cp_n0  = tid >> 3;
    const int cp_seg = tid & 7;
    const uint32_t dst0 = smem_u32(ws + cp_n0 * WS_STRIDE + cp_seg * 4);
    const float* src0 = w2 + (size_t)cp_n0 * D_ + cp_seg * 4;
    // per-it strides: dst += 32*WS_STRIDE floats (4608 B); src += 32*D_ floats.

#define ISSUE_W2_CHUNK(cc) do {                                                  \
        const uint32_t dbase = dst0 + (((cc) & 1) * WS_BUF) * 4;                 \
        const float* sbase = src0 + (size_t)(cc) * KC;                           \
        _Pragma("unroll")                                                        \
        for (int it = 0; it < 8; ++it)                                           \
            CP_ASYNC16(dbase + it * (32 * WS_STRIDE * 4), sbase + it * (32 * D_)); \
        CP_COMMIT();                                                             \
    } while (0)

    // issue w2 chunk 0
    ISSUE_W2_CHUNK(0);
    __syncthreads();   // se/sg visible

    // stage h chunk 0 into hs buffer 0 (8 gelu per thread)
    const int hm = tid >> 2;            // gene row 0..63
    const int hk = (tid & 3) * 8;       // k offset within chunk
    const float e_m = se[hm];
    {
        uint32_t* hrow = hs + hm * HS_STRIDE + hk;
#pragma unroll
        for (int j = 0; j < 8; ++j) {
            const float x = fmaf(e_m, __ldg(&w1[hk + j]), __ldg(&b1[hk + j]));
            hrow[j] = f2tf32(gelu_exact(x));
        }
    }

    float acc[2][8][4];
#pragma unroll
    for (int mi = 0; mi < 2; ++mi)
#pragma unroll
        for (int ni = 0; ni < 8; ++ni)
#pragma unroll
            for (int q = 0; q < 4; ++q) acc[mi][ni][q] = 0.0f;

    __syncthreads();   // h(0) visible

#pragma unroll
    for (int c = 0; c < 8; ++c) {
        CP_WAIT(0);        // chunk c landed
        __syncthreads();   // visibility + closes prior chunk's smem reads

        // issue w2 chunk c+1 into the other stage (read in iter c-1, safe)
        if (c + 1 < 8) ISSUE_W2_CHUNK(c + 1);

        // stage h chunk c+1 into the other hs buffer (overlaps MMAs below)
        if (c + 1 < 8) {
            const int k0 = (c + 1) * KC + hk;
            uint32_t* hrow = hs + ((c + 1) & 1) * HS_BUF + hm * HS_STRIDE + hk;
#pragma unroll
            for (int j = 0; j < 8; ++j) {
                const float x = fmaf(e_m, __ldg(&w1[k0 + j]), __ldg(&b1[k0 + j]));
                hrow[j] = f2tf32(gelu_exact(x));
            }
        }

        // MMAs on chunk c
        const uint32_t* hbuf = hs + (c & 1) * HS_BUF;
        const uint32_t* wbuf = ws + (c & 1) * WS_BUF;
#pragma unroll
        for (int ks = 0; ks < 4; ++ks) {
            const int k8 = ks * 8;
            uint32_t a[2][4];
#pragma unroll
            for (int mi = 0; mi < 2; ++mi) {
                const int rm = wm * 32 + mi * 16;
                a[mi][0] = hbuf[(rm + gq) * HS_STRIDE + k8 + tq];
                a[mi][1] = hbuf[(rm + 8 + gq) * HS_STRIDE + k8 + tq];
                a[mi][2] = hbuf[(rm + gq) * HS_STRIDE + k8 + tq + 4];
                a[mi][3] = hbuf[(rm + 8 + gq) * HS_STRIDE + k8 + tq + 4];
            }
#pragma unroll
            for (int ni = 0; ni < 8; ++ni) {
                const int nc = wn * 64 + ni * 8 + gq;
                const uint32_t b0 = wbuf[nc * WS_STRIDE + k8 + tq];
                const uint32_t b1r = wbuf[nc * WS_STRIDE + k8 + tq + 4];
#pragma unroll
                for (int mi = 0; mi < 2; ++mi)
                    mma_tf32(acc[mi][ni][0], acc[mi][ni][1], acc[mi][ni][2], acc[mi][ni][3],
                             a[mi][0], a[mi][1], a[mi][2], a[mi][3], b0, b1r);
            }
        }
    }

    // Epilogue: + b2 + gene_emb, zero invalid rows.
    float2 bb[8];
#pragma unroll
    for (int ni = 0; ni < 8; ++ni)
        bb[ni] = __ldg((const float2*)(b2 + wn * 64 + ni * 8 + 2 * tq));

#pragma unroll
    for (int mi = 0; mi < 2; ++mi) {
#pragma unroll
        for (int rr = 0; rr < 2; ++rr) {
            const int rrow = wm * 32 + mi * 16 + rr * 8 + gq;
            const int g = sg[rrow];
            float* orow = out + ((size_t)b * NTOK + 1 + j0 + rrow) * D_;
            if (g >= 0) {
                const float* gerow = gene_emb + (size_t)g * D_;
#pragma unroll
                for (int ni = 0; ni < 8; ++ni) {
                    const int col = wn * 64 + ni * 8 + 2 * tq;
                    const float2 ge = __ldg((const float2*)(gerow + col));
                    float2 rv;
                    rv.x = acc[mi][ni][2 * rr + 0] + bb[ni].x + ge.x;
                    rv.y = acc[mi][ni][2 * rr + 1] + bb[ni].y + ge.y;
                    *(float2*)(orow + col) = rv;
                }
            } else {
                const float2 z = make_float2(0.f, 0.f);
#pragma unroll
                for (int ni = 0; ni < 8; ++ni) {
                    const int col = wn * 64 + ni * 8 + 2 * tq;
                    *(float2*)(orow + col) = z;
                }
            }
        }
    }
}

// ---------------------------------------------------------------------------
extern "C" void kernel_launch(void* const* d_in, const int* in_sizes, int n_in,
                              void* d_out, int out_size) {
    const float* expr     = (const float*)d_in[0];
    const float* gene_emb = (const float*)d_in[1];
    const float* w1       = (const float*)d_in[2];
    const float* b1       = (const float*)d_in[3];
    const float* w2       = (const float*)d_in[4];
    const float* b2       = (const float*)d_in[5];
    const float* cls      = (const float*)d_in[6];
    float* out = (float*)d_out;

    const int tok_smem = (2 * HS_BUF + ST * WS_BUF) * (int)sizeof(uint32_t);  // ~91 KB
    cudaFuncSetAttribute(tok_mma_kernel, cudaFuncAttributeMaxDynamicSharedMemorySize,
                         tok_smem);

    select_kernel<<<B_, SEL_T>>>(expr, cls, out, (long long)out_size);
    tok_mma_kernel<<<dim3(K_ / MT, B_), 256, tok_smem>>>(expr, gene_emb, w1, b1,
                                                         w2, b2, out);
}